// round 4
// baseline (speedup 1.0000x reference)
#include <cuda_runtime.h>
#include <cuda_bf16.h>

#define BATCH 8
#define CIN   256
#define DQK   32
#define NPIX  4096   // 64*64

// Scratch (static device memory: allocation-free rule)
__device__ float g_q[(size_t)BATCH * NPIX * DQK];   // [b][i][d]   4 MB
__device__ float g_v[(size_t)BATCH * NPIX * CIN];   // [b][j][c]  33.5 MB
__device__ float g_m[(size_t)BATCH * NPIX];         // row max of energy

// ---------------------------------------------------------------------------
// Kernel 1: fused projection.  Out[j][o] = sum_c x[b][c][j] * W[o][c] + bias
// W rows 0..31 = q_w, rows 32..287 = v_w.  64x64 tile, k-chunks of 32.
// ---------------------------------------------------------------------------
__global__ __launch_bounds__(256) void proj_kernel(
    const float* __restrict__ x,
    const float* __restrict__ qw, const float* __restrict__ qb,
    const float* __restrict__ vw, const float* __restrict__ vb)
{
    int b  = blockIdx.z;
    int j0 = blockIdx.x * 64;
    int o0 = blockIdx.y * 64;

    __shared__ float Xs[32][64];
    __shared__ float Ws[32][65];   // Ws[kk][oo]

    int tid = threadIdx.x;
    int tx = tid & 15;      // -> output dim (4 outputs)
    int ty = tid >> 4;      // -> pixel dim  (4 pixels)

    float acc[4][4] = {};
    const float* xb = x + (size_t)b * CIN * NPIX;

    for (int c0 = 0; c0 < CIN; c0 += 32) {
        #pragma unroll
        for (int r = 0; r < 8; r++) {
            int idx = tid + r * 256;
            int kk = idx >> 6, jj = idx & 63;
            Xs[kk][jj] = xb[(size_t)(c0 + kk) * NPIX + j0 + jj];
        }
        #pragma unroll
        for (int r = 0; r < 8; r++) {
            int idx = tid + r * 256;
            int oo = idx >> 5, kk = idx & 31;
            int o = o0 + oo;
            float w = 0.f;
            if (o < DQK)          w = qw[o * CIN + c0 + kk];
            else if (o < DQK+CIN) w = vw[(o - DQK) * CIN + c0 + kk];
            Ws[kk][oo] = w;
        }
        __syncthreads();
        #pragma unroll
        for (int kk = 0; kk < 32; kk++) {
            float a[4], w[4];
            #pragma unroll
            for (int i = 0; i < 4; i++) a[i] = Xs[kk][ty * 4 + i];
            #pragma unroll
            for (int i = 0; i < 4; i++) w[i] = Ws[kk][tx * 4 + i];
            #pragma unroll
            for (int i = 0; i < 4; i++)
                #pragma unroll
                for (int o = 0; o < 4; o++)
                    acc[i][o] += a[i] * w[o];
        }
        __syncthreads();
    }

    #pragma unroll
    for (int i = 0; i < 4; i++) {
        int j = j0 + ty * 4 + i;
        #pragma unroll
        for (int oi = 0; oi < 4; oi++) {
            int o = o0 + tx * 4 + oi;
            if (o < DQK)
                g_q[((size_t)b * NPIX + j) * DQK + o] = acc[i][oi] + qb[o];
            else if (o < DQK + CIN)
                g_v[((size_t)b * NPIX + j) * CIN + (o - DQK)] = acc[i][oi] + vb[o - DQK];
        }
    }
}

// ---------------------------------------------------------------------------
// Kernel 2: per-row max of energy.  128 threads, 1 query each, q in registers,
// K tiles broadcast from smem.
// ---------------------------------------------------------------------------
__global__ __launch_bounds__(128) void rowmax_kernel()
{
    int b = blockIdx.y;
    int i = blockIdx.x * 128 + threadIdx.x;

    __shared__ float Ks[64][32];

    float q[DQK];
    const float* qrow = g_q + ((size_t)b * NPIX + i) * DQK;
    #pragma unroll
    for (int d = 0; d < DQK; d++) q[d] = qrow[d];

    float m = -1e30f;
    for (int j0 = 0; j0 < NPIX; j0 += 64) {
        const float* ksrc = g_q + ((size_t)b * NPIX + j0) * DQK;
        #pragma unroll
        for (int r = 0; r < 16; r++) {
            int idx = threadIdx.x + r * 128;
            Ks[idx >> 5][idx & 31] = ksrc[idx];
        }
        __syncthreads();
        #pragma unroll 4
        for (int j = 0; j < 64; j++) {
            float s0 = 0, s1 = 0, s2 = 0, s3 = 0;
            #pragma unroll
            for (int d = 0; d < DQK; d += 4) {
                s0 += q[d + 0] * Ks[j][d + 0];
                s1 += q[d + 1] * Ks[j][d + 1];
                s2 += q[d + 2] * Ks[j][d + 2];
                s3 += q[d + 3] * Ks[j][d + 3];
            }
            m = fmaxf(m, (s0 + s1) + (s2 + s3));
        }
        __syncthreads();
    }
    g_m[(size_t)b * NPIX + i] = m;
}

// ---------------------------------------------------------------------------
// Kernel 3: attention.  CTA = 32 queries, loop over 32-key tiles.
// S recomputed (m known), P = exp(S - m) into smem, O += P*V with 4q x 8c
// register tiles.  Epilogue: normalize, smem transpose, fused gamma*out + x.
// ---------------------------------------------------------------------------
__global__ __launch_bounds__(256) void attn_kernel(
    const float* __restrict__ x,
    const float* __restrict__ gamma,
    float* __restrict__ out)
{
    int b  = blockIdx.y;
    int i0 = blockIdx.x * 32;

    __shared__ __align__(16) float Qs[32][33];
    __shared__ __align__(16) float Ks[32][33];
    __shared__ __align__(16) float Ps[32][33];    // Ps[key][query]
    __shared__ __align__(16) float Vs[32][260];   // also reused as O transpose buffer
    __shared__ float lred[32][17];
    __shared__ float lbuf[32];

    int tid = threadIdx.x;

    // load Q tile
    #pragma unroll
    for (int r = 0; r < 4; r++) {
        int idx = tid + r * 256;
        Qs[idx >> 5][idx & 31] = g_q[((size_t)b * NPIX + i0) * DQK + idx];
    }

    // S-compute mapping: 16x16 threads, 2x2 micro tile
    int sx = tid & 15;   // key pair 2sx, 2sx+1
    int sy = tid >> 4;   // query pair 2sy, 2sy+1
    float m0 = g_m[(size_t)b * NPIX + i0 + 2 * sy];
    float m1 = g_m[(size_t)b * NPIX + i0 + 2 * sy + 1];
    float l0 = 0.f, l1 = 0.f;

    // PV mapping: queries {ty+8k}, channels {tx+32k}
    int tx = tid & 31;
    int ty = tid >> 5;
    float acc[4][8] = {};

    for (int j0 = 0; j0 < NPIX; j0 += 32) {
        // load K tile
        const float* ksrc = g_q + ((size_t)b * NPIX + j0) * DQK;
        #pragma unroll
        for (int r = 0; r < 4; r++) {
            int idx = tid + r * 256;
            Ks[idx >> 5][idx & 31] = ksrc[idx];
        }
        // load V tile (float4)
        const float4* vsrc = (const float4*)(g_v + ((size_t)b * NPIX + j0) * CIN);
        #pragma unroll
        for (int r = 0; r < 8; r++) {
            int idx = tid + r * 256;           // float4 index, 0..2047
            int j = idx >> 6, c4 = idx & 63;
            float4 v = vsrc[idx];
            *(float4*)&Vs[j][c4 * 4] = v;
        }
        __syncthreads();

        // S + exp
        float s00 = 0, s01 = 0, s10 = 0, s11 = 0;
        #pragma unroll
        for (int d = 0; d < DQK; d++) {
            float a0 = Qs[2 * sy][d],  a1 = Qs[2 * sy + 1][d];
            float b0 = Ks[2 * sx][d],  b1 = Ks[2 * sx + 1][d];
            s00 += a0 * b0; s01 += a0 * b1;
            s10 += a1 * b0; s11 += a1 * b1;
        }
        float p00 = __expf(s00 - m0), p01 = __expf(s01 - m0);
        float p10 = __expf(s10 - m1), p11 = __expf(s11 - m1);
        l0 += p00 + p01;
        l1 += p10 + p11;
        Ps[2 * sx][2 * sy]     = p00;  Ps[2 * sx + 1][2 * sy]     = p01;
        Ps[2 * sx][2 * sy + 1] = p10;  Ps[2 * sx + 1][2 * sy + 1] = p11;
        __syncthreads();

        // O += P * V
        #pragma unroll 4
        for (int j = 0; j < 32; j++) {
            float p[4];
            #pragma unroll
            for (int qi = 0; qi < 4; qi++) p[qi] = Ps[j][ty + 8 * qi];  // broadcast
            #pragma unroll
            for (int k = 0; k < 8; k++) {
                float v = Vs[j][tx + 32 * k];                           // conflict-free
                #pragma unroll
                for (int qi = 0; qi < 4; qi++) acc[qi][k] += p[qi] * v;
            }
        }
        __syncthreads();
    }

    // reduce l across the 16 key-columns per query
    lred[2 * sy][sx]     = l0;
    lred[2 * sy + 1][sx] = l1;
    __syncthreads();
    if (tid < 32) {
        float l = 0.f;
        #pragma unroll
        for (int k = 0; k < 16; k++) l += lred[tid][k];
        lbuf[tid] = 1.0f / l;
    }
    __syncthreads();

    // normalized O into Vs (reuse), then transpose-store fused with gamma*out + x
    #pragma unroll
    for (int qi = 0; qi < 4; qi++) {
        float inv = lbuf[ty + 8 * qi];
        #pragma unroll
        for (int k = 0; k < 8; k++)
            Vs[ty + 8 * qi][tx + 32 * k] = acc[qi][k] * inv;
    }
    __syncthreads();

    float g = gamma[0];
    int w = ty;        // warp id 0..7 -> channel stride
    int lane = tx;     // -> query (fast output axis)
    for (int c = w; c < CIN; c += 8) {
        float val = Vs[lane][c];
        size_t oidx = ((size_t)b * CIN + c) * NPIX + i0 + lane;
        out[oidx] = g * val + x[oidx];
    }
}

// ---------------------------------------------------------------------------
extern "C" void kernel_launch(void* const* d_in, const int* in_sizes, int n_in,
                              void* d_out, int out_size)
{
    const float* x     = (const float*)d_in[0];
    const float* q_w   = (const float*)d_in[1];
    const float* q_b   = (const float*)d_in[2];
    const float* v_w   = (const float*)d_in[3];
    const float* v_b   = (const float*)d_in[4];
    const float* gamma = (const float*)d_in[5];
    float* out = (float*)d_out;

    proj_kernel<<<dim3(NPIX / 64, 5, BATCH), 256>>>(x, q_w, q_b, v_w, v_b);
    rowmax_kernel<<<dim3(NPIX / 128, BATCH), 128>>>();
    attn_kernel<<<dim3(NPIX / 32, BATCH), 256>>>(x, gamma, out);
}

// round 5
// speedup vs baseline: 2.7504x; 2.7504x over previous
#include <cuda_runtime.h>
#include <cuda_bf16.h>

#define BATCH 8
#define CIN   256
#define DQK   32
#define NPIX  4096   // 64*64
#define QTILE 128
#define KTILE 64

// Scratch (static device memory: allocation-free rule)
__device__ float g_q[(size_t)BATCH * NPIX * DQK];   // [b][i][d]
__device__ float g_v[(size_t)BATCH * NPIX * CIN];   // [b][j][c]
__device__ float g_m[(size_t)BATCH * NPIX];         // |q_i|
__device__ float g_bm[BATCH];                       // max_j |q_j|

// ---------------------------------------------------------------------------
// helpers
// ---------------------------------------------------------------------------
__device__ __forceinline__ unsigned f2tf(float v) {
    unsigned r; asm("cvt.rna.tf32.f32 %0, %1;" : "=r"(r) : "f"(v)); return r;
}
__device__ __forceinline__ void mma8(float d[4], const unsigned a[4],
                                     unsigned b0, unsigned b1) {
    asm volatile(
        "mma.sync.aligned.m16n8k8.row.col.f32.tf32.tf32.f32 "
        "{%0,%1,%2,%3}, {%4,%5,%6,%7}, {%8,%9}, {%0,%1,%2,%3};"
        : "+f"(d[0]), "+f"(d[1]), "+f"(d[2]), "+f"(d[3])
        : "r"(a[0]), "r"(a[1]), "r"(a[2]), "r"(a[3]), "r"(b0), "r"(b1));
}

// ---------------------------------------------------------------------------
// Kernel 1: fused projection (unchanged).
// ---------------------------------------------------------------------------
__global__ __launch_bounds__(256) void proj_kernel(
    const float* __restrict__ x,
    const float* __restrict__ qw, const float* __restrict__ qb,
    const float* __restrict__ vw, const float* __restrict__ vb)
{
    int b  = blockIdx.z;
    int j0 = blockIdx.x * 64;
    int o0 = blockIdx.y * 64;

    __shared__ float Xs[32][64];
    __shared__ float Ws[32][65];

    int tid = threadIdx.x;
    int tx = tid & 15;
    int ty = tid >> 4;

    float acc[4][4] = {};
    const float* xb = x + (size_t)b * CIN * NPIX;

    for (int c0 = 0; c0 < CIN; c0 += 32) {
        #pragma unroll
        for (int r = 0; r < 8; r++) {
            int idx = tid + r * 256;
            int kk = idx >> 6, jj = idx & 63;
            Xs[kk][jj] = xb[(size_t)(c0 + kk) * NPIX + j0 + jj];
        }
        #pragma unroll
        for (int r = 0; r < 8; r++) {
            int idx = tid + r * 256;
            int oo = idx >> 5, kk = idx & 31;
            int o = o0 + oo;
            float w = 0.f;
            if (o < DQK)            w = qw[o * CIN + c0 + kk];
            else if (o < DQK + CIN) w = vw[(o - DQK) * CIN + c0 + kk];
            Ws[kk][oo] = w;
        }
        __syncthreads();
        #pragma unroll
        for (int kk = 0; kk < 32; kk++) {
            float a[4], w[4];
            #pragma unroll
            for (int i = 0; i < 4; i++) a[i] = Xs[kk][ty * 4 + i];
            #pragma unroll
            for (int i = 0; i < 4; i++) w[i] = Ws[kk][tx * 4 + i];
            #pragma unroll
            for (int i = 0; i < 4; i++)
                #pragma unroll
                for (int o = 0; o < 4; o++)
                    acc[i][o] += a[i] * w[o];
        }
        __syncthreads();
    }

    #pragma unroll
    for (int i = 0; i < 4; i++) {
        int j = j0 + ty * 4 + i;
        #pragma unroll
        for (int oi = 0; oi < 4; oi++) {
            int o = o0 + tx * 4 + oi;
            if (o < DQK)
                g_q[((size_t)b * NPIX + j) * DQK + o] = acc[i][oi] + qb[o];
            else if (o < DQK + CIN)
                g_v[((size_t)b * NPIX + j) * CIN + (o - DQK)] = acc[i][oi] + vb[o - DQK];
        }
    }
}

// ---------------------------------------------------------------------------
// Kernel 2: per-query norms + per-batch max norm (Cauchy-Schwarz softmax bound).
// ---------------------------------------------------------------------------
__global__ __launch_bounds__(256) void qnorm_kernel()
{
    int b = blockIdx.x;
    __shared__ float red[256];
    int tid = threadIdx.x;
    float mx = 0.f;
    for (int i = tid; i < NPIX; i += 256) {
        const float* q = g_q + ((size_t)b * NPIX + i) * DQK;
        float s = 0.f;
        #pragma unroll
        for (int d = 0; d < DQK; d++) s += q[d] * q[d];
        float n = sqrtf(s);
        g_m[(size_t)b * NPIX + i] = n;
        mx = fmaxf(mx, n);
    }
    red[tid] = mx;
    __syncthreads();
    for (int s = 128; s > 0; s >>= 1) {
        if (tid < s) red[tid] = fmaxf(red[tid], red[tid + s]);
        __syncthreads();
    }
    if (tid == 0) g_bm[b] = red[0];
}

// ---------------------------------------------------------------------------
// Kernel 3: tensor-core flash attention.
// CTA = 128 queries, 8 warps (warp w owns queries w*16..w*16+15).
// Per 64-key tile: S = QK^T via split-tf32 (3 mmas), P = exp(S-m) -> smem,
// O += P*V via tf32 mma.  Epilogue: normalize + smem transpose + gamma*o + x.
// ---------------------------------------------------------------------------
__global__ __launch_bounds__(256, 1) void attn_tc_kernel(
    const float* __restrict__ x,
    const float* __restrict__ gamma,
    float* __restrict__ out)
{
    extern __shared__ char sm_raw[];
    float (*Kh)[36]  = (float(*)[36])(sm_raw);                 //  9216 B
    float (*Kl)[36]  = (float(*)[36])(sm_raw + 9216);          //  9216 B
    float (*Vs)[264] = (float(*)[264])(sm_raw + 18432);        // 67584 B
    float (*Ps)[68]  = (float(*)[68])(sm_raw + 86016);         // 34816 B  (tot 120832)
    float (*Ot)[132] = (float(*)[132])(sm_raw);                // epilogue alias

    int b   = blockIdx.y;
    int i0  = blockIdx.x * QTILE;
    int tid = threadIdx.x;
    int w    = tid >> 5;
    int lane = tid & 31;
    int g = lane >> 2;      // groupID
    int t = lane & 3;       // threadID_in_group
    int q0 = w * 16;

    const float* gq_b = g_q + (size_t)b * NPIX * DQK;

    // softmax upper bounds for this thread's two query rows
    float Mb = g_bm[b];
    float m0 = g_m[(size_t)b * NPIX + i0 + q0 + g] * Mb;
    float m1 = g_m[(size_t)b * NPIX + i0 + q0 + g + 8] * Mb;

    // Q fragments (hi/lo split), persistent: A[kc] covers dims kc*8..kc*8+7
    unsigned qh[4][4], ql[4][4];
    #pragma unroll
    for (int kc = 0; kc < 4; kc++) {
        int r0 = i0 + q0 + g, r1 = r0 + 8;
        int c0 = kc * 8 + t,  c1 = c0 + 4;
        float v00 = gq_b[(size_t)r0 * DQK + c0];
        float v10 = gq_b[(size_t)r1 * DQK + c0];
        float v01 = gq_b[(size_t)r0 * DQK + c1];
        float v11 = gq_b[(size_t)r1 * DQK + c1];
        qh[kc][0] = f2tf(v00); ql[kc][0] = f2tf(v00 - __uint_as_float(qh[kc][0]));
        qh[kc][1] = f2tf(v10); ql[kc][1] = f2tf(v10 - __uint_as_float(qh[kc][1]));
        qh[kc][2] = f2tf(v01); ql[kc][2] = f2tf(v01 - __uint_as_float(qh[kc][2]));
        qh[kc][3] = f2tf(v11); ql[kc][3] = f2tf(v11 - __uint_as_float(qh[kc][3]));
    }

    float acc[32][4];
    #pragma unroll
    for (int nt = 0; nt < 32; nt++)
        #pragma unroll
        for (int k = 0; k < 4; k++) acc[nt][k] = 0.f;
    float l0 = 0.f, l1 = 0.f;

    const float4* vbase = (const float4*)(g_v + (size_t)b * NPIX * CIN);

    for (int j0 = 0; j0 < NPIX; j0 += KTILE) {
        __syncthreads();   // protect Vs/Kh/Ps from previous readers

        // --- load K tile (64x32) with hi/lo tf32 split ---
        #pragma unroll
        for (int r = 0; r < 8; r++) {
            int idx = tid + r * 256;
            int key = idx >> 5, d = idx & 31;
            float v = gq_b[(size_t)(j0 + key) * DQK + d];
            unsigned h = f2tf(v);
            Kh[key][d] = __uint_as_float(h);
            Kl[key][d] = __uint_as_float(f2tf(v - __uint_as_float(h)));
        }
        // --- load V tile (64x256) as tf32 ---
        #pragma unroll
        for (int r = 0; r < 16; r++) {
            int idx = tid + r * 256;        // float4 index over 64*64
            int key = idx >> 6, c4 = idx & 63;
            float4 v = vbase[(size_t)j0 * 64 + idx];
            float4 o;
            o.x = __uint_as_float(f2tf(v.x));
            o.y = __uint_as_float(f2tf(v.y));
            o.z = __uint_as_float(f2tf(v.z));
            o.w = __uint_as_float(f2tf(v.w));
            *(float4*)&Vs[key][c4 * 4] = o;
        }
        __syncthreads();

        // --- S = Q K^T (split tf32), P = exp(S-m), store to Ps ---
        #pragma unroll
        for (int nt = 0; nt < 8; nt++) {
            float d[4] = {0.f, 0.f, 0.f, 0.f};
            #pragma unroll
            for (int kc = 0; kc < 4; kc++) {
                unsigned bh0 = __float_as_uint(Kh[nt * 8 + g][kc * 8 + t]);
                unsigned bh1 = __float_as_uint(Kh[nt * 8 + g][kc * 8 + t + 4]);
                unsigned bl0 = __float_as_uint(Kl[nt * 8 + g][kc * 8 + t]);
                unsigned bl1 = __float_as_uint(Kl[nt * 8 + g][kc * 8 + t + 4]);
                mma8(d, qh[kc], bh0, bh1);
                mma8(d, qh[kc], bl0, bl1);
                mma8(d, ql[kc], bh0, bh1);
            }
            float p0 = __expf(d[0] - m0);
            float p1 = __expf(d[1] - m0);
            float p2 = __expf(d[2] - m1);
            float p3 = __expf(d[3] - m1);
            l0 += p0 + p1;
            l1 += p2 + p3;
            // rows: q0+g (c0,c1), q0+g+8 (c2,c3); cols: nt*8 + 2t, +1
            float2* s0 = (float2*)&Ps[q0 + g][nt * 8 + 2 * t];
            float2* s1 = (float2*)&Ps[q0 + g + 8][nt * 8 + 2 * t];
            *s0 = make_float2(__uint_as_float(f2tf(p0)), __uint_as_float(f2tf(p1)));
            *s1 = make_float2(__uint_as_float(f2tf(p2)), __uint_as_float(f2tf(p3)));
        }
        __syncthreads();

        // --- O += P V : A = P[16 x 64] (8 k-chunks), B = V[64 x 256] ---
        #pragma unroll
        for (int kc = 0; kc < 8; kc++) {
            unsigned a[4];
            a[0] = __float_as_uint(Ps[q0 + g][kc * 8 + t]);
            a[1] = __float_as_uint(Ps[q0 + g + 8][kc * 8 + t]);
            a[2] = __float_as_uint(Ps[q0 + g][kc * 8 + t + 4]);
            a[3] = __float_as_uint(Ps[q0 + g + 8][kc * 8 + t + 4]);
            #pragma unroll
            for (int nt = 0; nt < 32; nt++) {
                unsigned b0 = __float_as_uint(Vs[kc * 8 + t][nt * 8 + g]);
                unsigned b1 = __float_as_uint(Vs[kc * 8 + t + 4][nt * 8 + g]);
                mma8(acc[nt], a, b0, b1);
            }
        }
    }

    // --- reduce l over the 4 lanes of each quad (cols of the row) ---
    l0 += __shfl_xor_sync(0xffffffffu, l0, 1);
    l0 += __shfl_xor_sync(0xffffffffu, l0, 2);
    l1 += __shfl_xor_sync(0xffffffffu, l1, 1);
    l1 += __shfl_xor_sync(0xffffffffu, l1, 2);
    float inv0 = 1.f / l0, inv1 = 1.f / l1;
    float gam = gamma[0];

    // --- epilogue: 4 chunks of 64 channels, smem transpose, fused residual ---
    #pragma unroll
    for (int cc = 0; cc < 4; cc++) {
        __syncthreads();
        #pragma unroll
        for (int nt2 = 0; nt2 < 8; nt2++) {
            int nt = cc * 8 + nt2;
            Ot[nt2 * 8 + 2 * t + 0][q0 + g]     = acc[nt][0] * inv0;
            Ot[nt2 * 8 + 2 * t + 1][q0 + g]     = acc[nt][1] * inv0;
            Ot[nt2 * 8 + 2 * t + 0][q0 + g + 8] = acc[nt][2] * inv1;
            Ot[nt2 * 8 + 2 * t + 1][q0 + g + 8] = acc[nt][3] * inv1;
        }
        __syncthreads();
        #pragma unroll
        for (int r = 0; r < 8; r++) {
            int idx = tid + r * 256;         // 64 ch x 32 float4-of-queries
            int cl = idx >> 5, q4 = idx & 31;
            int c = cc * 64 + cl;
            size_t base = ((size_t)b * CIN + c) * NPIX + i0 + q4 * 4;
            float4 o = *(float4*)&Ot[cl][q4 * 4];
            float4 xv = *(const float4*)(x + base);
            float4 rv;
            rv.x = gam * o.x + xv.x;
            rv.y = gam * o.y + xv.y;
            rv.z = gam * o.z + xv.z;
            rv.w = gam * o.w + xv.w;
            *(float4*)(out + base) = rv;
        }
    }
}

// ---------------------------------------------------------------------------
extern "C" void kernel_launch(void* const* d_in, const int* in_sizes, int n_in,
                              void* d_out, int out_size)
{
    const float* x     = (const float*)d_in[0];
    const float* q_w   = (const float*)d_in[1];
    const float* q_b   = (const float*)d_in[2];
    const float* v_w   = (const float*)d_in[3];
    const float* v_b   = (const float*)d_in[4];
    const float* gamma = (const float*)d_in[5];
    float* out = (float*)d_out;

    const int ATTN_SMEM = 120832;
    cudaFuncSetAttribute(attn_tc_kernel,
                         cudaFuncAttributeMaxDynamicSharedMemorySize, ATTN_SMEM);

    proj_kernel<<<dim3(NPIX / 64, 5, BATCH), 256>>>(x, q_w, q_b, v_w, v_b);
    qnorm_kernel<<<BATCH, 256>>>();
    attn_tc_kernel<<<dim3(NPIX / QTILE, BATCH), 256, ATTN_SMEM>>>(x, gamma, out);
}